// round 11
// baseline (speedup 1.0000x reference)
#include <cuda_runtime.h>
#include <cuda_bf16.h>
#include <cstdint>

// ChannelBlockImportanceGate: forward value == hard top-k block mask.
// features [8,256,132,132] f32, enabled int32. BLOCK=8 -> 17x17=289 blocks,
// keep = 72. Ties: lower flat index wins (lax.top_k).
//
// R11: channel-pair pipelining. Each CTA handles channels (2b, 2b+1)
// sequentially; channel B's cp.async chunk loop interleaves channel A's
// pixel stores (one chunk read + one chunk-equivalent write per iteration)
// so the read and write streams mix steadily instead of alternating.
// Consume pass + selection byte-identical to the R6-passing kernel.

#define HH   132
#define WW   132
#define NBX  17
#define NBLK 289
#define KEEP 72
#define NPIX (HH*WW)
#define NTHREADS 256
#define CHUNK_ROWS 16
#define NCHUNK 9
#define ROW_F4 33           // 132 floats = 33 float4 per row

__device__ __forceinline__ void cp_async16(void* smem_ptr, const void* gptr) {
    uint32_t s = (uint32_t)__cvta_generic_to_shared(smem_ptr);
    asm volatile("cp.async.cg.shared.global [%0], [%1], 16;\n"
                 :: "r"(s), "l"(gptr));
}
#define CP_COMMIT() asm volatile("cp.async.commit_group;\n" ::: "memory")
#define CP_WAIT1()  asm volatile("cp.async.wait_group 1;\n" ::: "memory")
#define CP_WAIT0()  asm volatile("cp.async.wait_group 0;\n" ::: "memory")

struct SelShared {
    float pooled[NBLK];
    int   hist[32];
    float wmin[8], wmax[8];
    float minv, scale;
    int   bb, chi, mcnt;
    int   bblist[NBLK];
};

// consume one staged chunk into per-row block partials (R6 canonical tree)
__device__ __forceinline__ void consume_chunk(const float* bf, float* rbs,
                                              int r0, int nr, int tid)
{
    int tasks = nr * NBX;
    for (int t = tid; t < tasks; t += NTHREADS) {
        int rl = t / NBX;
        int bx = t - rl * NBX;
        const float* row = bf + rl * WW;
        float4 a = *(const float4*)(row + bx * 8);
        float4 b4;
        if (bx < 16) b4 = *(const float4*)(row + bx * 8 + 4);
        else         b4 = make_float4(0.f, 0.f, 0.f, 0.f);
        rbs[(r0 + rl) * NBX + bx] =
              ((fabsf(a.x) + fabsf(b4.x)) + (fabsf(a.z) + fabsf(b4.z)))
            + ((fabsf(a.y) + fabsf(b4.y)) + (fabsf(a.w) + fabsf(b4.w)));
    }
}

// stores pixel rows [r0, r0+nr) of one channel from its block mask
__device__ __forceinline__ void store_rows(float* outc, const float* hardm,
                                           int r0, int nr, int tid)
{
    float4* o4 = (float4*)outc + r0 * ROW_F4;
    int n = nr * ROW_F4;
    for (int i = tid; i < n; i += NTHREADS) {
        int rl = i / ROW_F4;
        int x4 = i - rl * ROW_F4;
        float v = hardm[((r0 + rl) >> 3) * NBX + (x4 >> 1)];
        o4[i] = make_float4(v, v, v, v);
    }
}

// Phases B..rank: rbs -> hardm. Byte-identical math to R6.
__device__ __forceinline__ void select_mask(const float* rbs, float* hardm,
                                            SelShared& ss, int tid, int warp, int lane)
{
    if (tid < 32) ss.hist[tid] = 0;
    if (tid == 0) ss.mcnt = 0;

    // Phase B: block sums (linear over 8 rows, rows>=132 are pad) + min/max
    float lmin = 3.4e38f, lmax = -3.4e38f;
    for (int b = tid; b < NBLK; b += NTHREADS) {
        int by = b / NBX;
        int bx = b - by * NBX;
        int y0 = by * 8;
        float s = 0.0f;
        #pragma unroll
        for (int r = 0; r < 8; r++) {
            int y = y0 + r;
            if (y < HH) s += rbs[y * NBX + bx];
        }
        ss.pooled[b] = s;
        lmin = fminf(lmin, s);
        lmax = fmaxf(lmax, s);
    }
    #pragma unroll
    for (int off = 16; off > 0; off >>= 1) {
        lmin = fminf(lmin, __shfl_down_sync(0xffffffffu, lmin, off));
        lmax = fmaxf(lmax, __shfl_down_sync(0xffffffffu, lmax, off));
    }
    if (lane == 0) { ss.wmin[warp] = lmin; ss.wmax[warp] = lmax; }
    __syncthreads();

    if (warp == 0) {
        float mn = (lane < 8) ? ss.wmin[lane] : 3.4e38f;
        float mx = (lane < 8) ? ss.wmax[lane] : -3.4e38f;
        #pragma unroll
        for (int off = 4; off > 0; off >>= 1) {
            mn = fminf(mn, __shfl_down_sync(0xffffffffu, mn, off));
            mx = fmaxf(mx, __shfl_down_sync(0xffffffffu, mx, off));
        }
        if (lane == 0) {
            float r = mx - mn;
            ss.minv  = mn;
            ss.scale = (r > 0.0f) ? (32.0f / r) : 0.0f;
        }
    }
    __syncthreads();

    // histogram
    {
        float minv = ss.minv, scale = ss.scale;
        for (int b = tid; b < NBLK; b += NTHREADS) {
            int bin = min((int)((ss.pooled[b] - minv) * scale), 31);
            atomicAdd(&ss.hist[bin], 1);
        }
    }
    __syncthreads();

    // warp 0: suffix scan -> boundary bin bb, count strictly above (chi)
    if (warp == 0) {
        int cge = ss.hist[lane];
        #pragma unroll
        for (int off = 1; off < 32; off <<= 1) {
            int t = __shfl_down_sync(0xffffffffu, cge, off);
            if (lane + off < 32) cge += t;
        }
        int cgt = __shfl_down_sync(0xffffffffu, cge, 1);
        if (lane == 31) cgt = 0;
        if (cgt < KEEP && cge >= KEEP) { ss.bb = lane; ss.chi = cgt; }
    }
    __syncthreads();

    // classify; collect boundary-bin items
    {
        float minv = ss.minv, scale = ss.scale;
        int bb = ss.bb;
        for (int b = tid; b < NBLK; b += NTHREADS) {
            int bin = min((int)((ss.pooled[b] - minv) * scale), 31);
            if (bin > bb)      hardm[b] = 1.0f;
            else if (bin < bb) hardm[b] = 0.0f;
            else               ss.bblist[atomicAdd(&ss.mcnt, 1)] = b;
        }
    }
    __syncthreads();

    // exact rank inside boundary bin (tie: lower index wins)
    {
        int m = ss.mcnt;
        int budget = KEEP - ss.chi;
        for (int it = tid; it < m; it += NTHREADS) {
            int i = ss.bblist[it];
            float vi = ss.pooled[i];
            int c = 0;
            for (int j = 0; j < m; j++) {
                int jj = ss.bblist[j];
                float vj = ss.pooled[jj];
                c += (vj > vi) || (vj == vi && jj < i);
            }
            hardm[i] = (c < budget) ? 1.0f : 0.0f;
        }
    }
    __syncthreads();
}

__global__ __launch_bounds__(NTHREADS)
void gate_kernel(const float* __restrict__ in,
                 const int*  __restrict__ enabled,
                 float* __restrict__ out,
                 int n_ch)
{
    const int tid  = threadIdx.x;
    const int warp = tid >> 5;
    const int lane = tid & 31;
    const int chA  = blockIdx.x * 2;
    const int chB  = chA + 1;
    const bool hasB = (chB < n_ch);

    float* outA = out + (long long)chA * NPIX;
    float* outB = out + (long long)chB * NPIX;

    if (*enabled == 0) {
        float4 ones = make_float4(1.f, 1.f, 1.f, 1.f);
        float4* oa = (float4*)outA;
        for (int p = tid; p < NPIX / 4; p += NTHREADS) oa[p] = ones;
        if (hasB) {
            float4* ob = (float4*)outB;
            for (int p = tid; p < NPIX / 4; p += NTHREADS) ob[p] = ones;
        }
        return;
    }

    __shared__ float4 buf[2][CHUNK_ROWS * ROW_F4];   // cp.async staging
    __shared__ float  rbs[HH * NBX];
    __shared__ float  hardmA[NBLK];
    __shared__ float  hardmB[NBLK];
    __shared__ SelShared ss;

    const float4* srcA = (const float4*)(in + (long long)chA * NPIX);
    const float4* srcB = (const float4*)(in + (long long)chB * NPIX);

    // ================= Channel A: read + pool (R6 double-buffered loop) =====
    {
        int n4 = CHUNK_ROWS * ROW_F4;
        for (int i = tid; i < n4; i += NTHREADS)
            cp_async16(&buf[0][i], srcA + i);
        CP_COMMIT();
    }
    for (int c = 0; c < NCHUNK; c++) {
        int r0 = c * CHUNK_ROWS;
        int nr = min(CHUNK_ROWS, HH - r0);
        if (c + 1 < NCHUNK) {
            int r0n = (c + 1) * CHUNK_ROWS;
            int nrn = min(CHUNK_ROWS, HH - r0n);
            int n4  = nrn * ROW_F4;
            const float4* g = srcA + r0n * ROW_F4;
            float4* b = buf[(c + 1) & 1];
            for (int i = tid; i < n4; i += NTHREADS)
                cp_async16(&b[i], g + i);
            CP_COMMIT();
            CP_WAIT1();
        } else {
            CP_WAIT0();
        }
        __syncthreads();
        consume_chunk((const float*)buf[c & 1], rbs, r0, nr, tid);
        __syncthreads();
    }

    // ================= Channel A: select ====================================
    select_mask(rbs, hardmA, ss, tid, warp, lane);

    if (hasB) {
        // prefill B chunk 0 -- flies while we start storing A
        {
            int n4 = CHUNK_ROWS * ROW_F4;
            for (int i = tid; i < n4; i += NTHREADS)
                cp_async16(&buf[0][i], srcB + i);
            CP_COMMIT();
        }

        // ============ Channel B read loop with channel A stores mixed in ====
        for (int c = 0; c < NCHUNK; c++) {
            int r0 = c * CHUNK_ROWS;
            int nr = min(CHUNK_ROWS, HH - r0);
            if (c + 1 < NCHUNK) {
                int r0n = (c + 1) * CHUNK_ROWS;
                int nrn = min(CHUNK_ROWS, HH - r0n);
                int n4  = nrn * ROW_F4;
                const float4* g = srcB + r0n * ROW_F4;
                float4* b = buf[(c + 1) & 1];
                for (int i = tid; i < n4; i += NTHREADS)
                    cp_async16(&b[i], g + i);
                CP_COMMIT();
                CP_WAIT1();
            } else {
                CP_WAIT0();
            }
            __syncthreads();
            consume_chunk((const float*)buf[c & 1], rbs, r0, nr, tid);
            // interleaved: store the SAME rows of channel A (one chunk of
            // writes per chunk of reads -> steady mixed stream)
            store_rows(outA, hardmA, r0, nr, tid);
            __syncthreads();
        }

        // ============ Channel B: select + store =============================
        select_mask(rbs, hardmB, ss, tid, warp, lane);
        store_rows(outB, hardmB, 0, HH, tid);
    } else {
        store_rows(outA, hardmA, 0, HH, tid);
    }
}

extern "C" void kernel_launch(void* const* d_in, const int* in_sizes, int n_in,
                              void* d_out, int out_size)
{
    const float* features = (const float*)d_in[0];
    const int*   enabled  = (const int*)d_in[1];
    float* out = (float*)d_out;

    const int n_channels = out_size / NPIX;           // 2048
    const int grid = (n_channels + 1) / 2;            // 1024
    gate_kernel<<<grid, NTHREADS>>>(features, enabled, out, n_channels);
}

// round 12
// speedup vs baseline: 1.1592x; 1.1592x over previous
#include <cuda_runtime.h>
#include <cuda_bf16.h>
#include <cstdint>

// ChannelBlockImportanceGate: forward value == hard top-k block mask.
// features [8,256,132,132] f32, enabled int32. BLOCK=8 -> 17x17=289 blocks,
// keep = 72. Ties: lower flat index wins (lax.top_k).
//
// R12: R6 (best known) with Phase B folded into the chunk loop. Each 16-row
// chunk covers exactly two block-rows, so pooled[] is finalized per-chunk
// from a 1KB chunk-local rbs (same row order -> bitwise identical sums).
// smem 30KB -> 22KB: occupancy goes smem-capped(7) -> thread-capped(8).

#define HH   132
#define WW   132
#define NBX  17
#define NBLK 289
#define KEEP 72
#define NPIX (HH*WW)
#define NTHREADS 256
#define CHUNK_ROWS 16
#define NCHUNK 9
#define ROW_F4 33           // 132 floats = 33 float4 per row

__device__ __forceinline__ void cp_async16(void* smem_ptr, const void* gptr) {
    uint32_t s = (uint32_t)__cvta_generic_to_shared(smem_ptr);
    asm volatile("cp.async.cg.shared.global [%0], [%1], 16;\n"
                 :: "r"(s), "l"(gptr));
}
#define CP_COMMIT() asm volatile("cp.async.commit_group;\n" ::: "memory")
#define CP_WAIT1()  asm volatile("cp.async.wait_group 1;\n" ::: "memory")
#define CP_WAIT0()  asm volatile("cp.async.wait_group 0;\n" ::: "memory")

__global__ __launch_bounds__(NTHREADS)
void gate_kernel(const float* __restrict__ in,
                 const int*  __restrict__ enabled,
                 float* __restrict__ out)
{
    const int bc = blockIdx.x;
    const long long base = (long long)bc * NPIX;
    const int tid  = threadIdx.x;
    const int warp = tid >> 5;
    const int lane = tid & 31;

    if (*enabled == 0) {
        float4 ones = make_float4(1.f, 1.f, 1.f, 1.f);
        float4* o4 = (float4*)(out + base);
        for (int p = tid; p < NPIX / 4; p += NTHREADS) o4[p] = ones;
        return;
    }

    __shared__ float4 buf[2][CHUNK_ROWS * ROW_F4];   // 16.9 KB staging
    __shared__ float  rbsl[CHUNK_ROWS * NBX];        // chunk-local partials, 1.1 KB
    __shared__ float  pooled[NBLK];
    __shared__ float  hardm[NBLK];
    __shared__ int    hist[32];
    __shared__ float  wmin[8], wmax[8];
    __shared__ float  s_minv, s_scale;
    __shared__ int    s_bb, s_chi, s_mcnt;
    __shared__ int    bblist[NBLK];

    if (tid < 32) hist[tid] = 0;
    if (tid == 0) s_mcnt = 0;

    const float4* src4 = (const float4*)(in + base);

    // ---- Phase A+B fused: double-buffered cp.async; per-chunk pooled fold.
    {
        int n4 = CHUNK_ROWS * ROW_F4;
        for (int i = tid; i < n4; i += NTHREADS)
            cp_async16(&buf[0][i], src4 + i);
        CP_COMMIT();
    }
    for (int c = 0; c < NCHUNK; c++) {
        int r0 = c * CHUNK_ROWS;
        int nr = min(CHUNK_ROWS, HH - r0);
        if (c + 1 < NCHUNK) {
            int r0n = (c + 1) * CHUNK_ROWS;
            int nrn = min(CHUNK_ROWS, HH - r0n);
            int n4  = nrn * ROW_F4;
            const float4* g = src4 + r0n * ROW_F4;
            float4* b = buf[(c + 1) & 1];
            for (int i = tid; i < n4; i += NTHREADS)
                cp_async16(&b[i], g + i);
            CP_COMMIT();
            CP_WAIT1();
        } else {
            CP_WAIT0();
        }
        __syncthreads();          // staged data visible; prior pooled fold done

        // consume chunk c: per-(local row, bx) partial, canonical tree
        const float* bf = (const float*)buf[c & 1];
        int tasks = nr * NBX;
        for (int t = tid; t < tasks; t += NTHREADS) {
            int rl = t / NBX;
            int bx = t - rl * NBX;
            const float* row = bf + rl * WW;
            float4 a = *(const float4*)(row + bx * 8);
            float4 b4;
            if (bx < 16) b4 = *(const float4*)(row + bx * 8 + 4);
            else         b4 = make_float4(0.f, 0.f, 0.f, 0.f);
            rbsl[rl * NBX + bx] =
                  ((fabsf(a.x) + fabsf(b4.x)) + (fabsf(a.z) + fabsf(b4.z)))
                + ((fabsf(a.y) + fabsf(b4.y)) + (fabsf(a.w) + fabsf(b4.w)));
        }
        __syncthreads();          // rbsl complete for chunk c

        // pooled fold: chunk c holds block-rows 2c (rows 0..7) and 2c+1
        // (rows 8..15); tail chunk 8 holds only block-row 16 (4 valid rows).
        // Same increasing-row order as R6's Phase B -> bitwise identical.
        int nb = (c == NCHUNK - 1) ? NBX : 2 * NBX;
        if (tid < nb) {
            int lr = tid / NBX;               // local block-row 0/1
            int bx = tid - lr * NBX;
            int nr2 = (c == NCHUNK - 1) ? 4 : 8;
            float s = 0.0f;
            #pragma unroll
            for (int r = 0; r < 8; r++)
                if (r < nr2) s += rbsl[(lr * 8 + r) * NBX + bx];
            pooled[c * 34 + tid] = s;         // b = (2c+lr)*17 + bx = c*34 + tid
        }
        // fold for chunk c is protected by the NEXT iteration's first barrier
    }
    __syncthreads();              // last fold visible

    // ---- min/max over pooled
    float lmin = 3.4e38f, lmax = -3.4e38f;
    for (int b = tid; b < NBLK; b += NTHREADS) {
        float s = pooled[b];
        lmin = fminf(lmin, s);
        lmax = fmaxf(lmax, s);
    }
    #pragma unroll
    for (int off = 16; off > 0; off >>= 1) {
        lmin = fminf(lmin, __shfl_down_sync(0xffffffffu, lmin, off));
        lmax = fmaxf(lmax, __shfl_down_sync(0xffffffffu, lmax, off));
    }
    if (lane == 0) { wmin[warp] = lmin; wmax[warp] = lmax; }
    __syncthreads();

    // ---- warp 0: global min/max -> bin scale
    if (warp == 0) {
        float mn = (lane < 8) ? wmin[lane] : 3.4e38f;
        float mx = (lane < 8) ? wmax[lane] : -3.4e38f;
        #pragma unroll
        for (int off = 4; off > 0; off >>= 1) {
            mn = fminf(mn, __shfl_down_sync(0xffffffffu, mn, off));
            mx = fmaxf(mx, __shfl_down_sync(0xffffffffu, mx, off));
        }
        if (lane == 0) {
            float r = mx - mn;
            s_minv  = mn;
            s_scale = (r > 0.0f) ? (32.0f / r) : 0.0f;
        }
    }
    __syncthreads();

    // ---- histogram
    {
        float minv = s_minv, scale = s_scale;
        for (int b = tid; b < NBLK; b += NTHREADS) {
            int bin = min((int)((pooled[b] - minv) * scale), 31);
            atomicAdd(&hist[bin], 1);
        }
    }
    __syncthreads();

    // ---- warp 0: suffix scan -> boundary bin bb, count strictly above (chi)
    if (warp == 0) {
        int cge = hist[lane];
        #pragma unroll
        for (int off = 1; off < 32; off <<= 1) {
            int t = __shfl_down_sync(0xffffffffu, cge, off);
            if (lane + off < 32) cge += t;
        }
        int cgt = __shfl_down_sync(0xffffffffu, cge, 1);
        if (lane == 31) cgt = 0;
        if (cgt < KEEP && cge >= KEEP) { s_bb = lane; s_chi = cgt; }
    }
    __syncthreads();

    // ---- classify; collect boundary-bin items
    {
        float minv = s_minv, scale = s_scale;
        int bb = s_bb;
        for (int b = tid; b < NBLK; b += NTHREADS) {
            int bin = min((int)((pooled[b] - minv) * scale), 31);
            if (bin > bb)      hardm[b] = 1.0f;
            else if (bin < bb) hardm[b] = 0.0f;
            else               bblist[atomicAdd(&s_mcnt, 1)] = b;
        }
    }
    __syncthreads();

    // ---- exact rank inside boundary bin (tie: lower index wins)
    {
        int m = s_mcnt;
        int budget = KEEP - s_chi;
        for (int it = tid; it < m; it += NTHREADS) {
            int i = bblist[it];
            float vi = pooled[i];
            int c = 0;
            for (int j = 0; j < m; j++) {
                int jj = bblist[j];
                float vj = pooled[jj];
                c += (vj > vi) || (vj == vi && jj < i);
            }
            hardm[i] = (c < budget) ? 1.0f : 0.0f;
        }
    }
    __syncthreads();

    // ---- Phase D: expand to pixels, float4 stores (R6 form)
    for (int by = warp; by < NBX; by += 8) {
        float  mv  = hardm[by * NBX + (lane >> 1)];
        float  m16 = hardm[by * NBX + 16];
        float4 v4  = make_float4(mv, mv, mv, mv);
        float4 v16 = make_float4(m16, m16, m16, m16);
        int ylim = min(HH - by * 8, 8);
        float* obase = out + base + (by * 8) * WW;
        for (int r = 0; r < ylim; r++) {
            float* orow = obase + r * WW;
            *(float4*)(orow + lane * 4) = v4;
            if (lane == 0) *(float4*)(orow + 128) = v16;
        }
    }
}

extern "C" void kernel_launch(void* const* d_in, const int* in_sizes, int n_in,
                              void* d_out, int out_size)
{
    const float* features = (const float*)d_in[0];
    const int*   enabled  = (const int*)d_in[1];
    float* out = (float*)d_out;

    const int n_channels = out_size / NPIX;   // 2048
    gate_kernel<<<n_channels, NTHREADS>>>(features, enabled, out);
}